// round 9
// baseline (speedup 1.0000x reference)
#include <cuda_runtime.h>
#include <cstdint>

#define BB 64
#define TT 2048
#define DD 512
#define UU 32

// Scratch (device globals: allowed, no runtime allocation)
__device__ float    g_logits[(BB * TT + 16) * UU];   // ~16.8 MB, padded for prefetch overrun
__device__ unsigned g_bps[BB * (TT / 4) * UU];       // 4 MB: backpointers, 4 steps packed per u32

// ---------------------------------------------------------------------------
// Kernel 1: logits = x @ W + bias, fp32 via packed f32x2 FMA.
// grid = 64 batches * 16 chunks of 128 rows, block = 256 threads (8 warps).
// Warp w owns d in [64w, 64w+64) with W column pairs in registers.
// Rows with t >= nwords[b] are skipped (never consumed by Viterbi).
// ---------------------------------------------------------------------------
__global__ void __launch_bounds__(256, 2) gemm_kernel(
    const float* __restrict__ x, const float* __restrict__ W,
    const float* __restrict__ bias, const int* __restrict__ nw)
{
    const int b    = blockIdx.x >> 4;
    const int t0   = (blockIdx.x & 15) * 128;
    const int len  = nw[b];
    if (t0 >= len) return;                       // uniform per block

    const int w    = threadIdx.x >> 5;
    const int lane = threadIdx.x & 31;
    const int d0   = w * 64;

    // W pairs in registers: wp[i] = (W[d0+2i][lane], W[d0+2i+1][lane])
    unsigned long long wp[32];
#pragma unroll
    for (int i = 0; i < 32; i++) {
        float lo = W[(d0 + 2 * i) * UU + lane];
        float hi = W[(d0 + 2 * i + 1) * UU + lane];
        asm("mov.b64 %0, {%1, %2};" : "=l"(wp[i]) : "f"(lo), "f"(hi));
    }

    __shared__ __align__(16) float xs[DD];
    __shared__ float part[8][32];
    const float bj = bias[lane];
    const int rmax = min(128, len - t0);

    for (int r = 0; r < rmax; r++) {
        const int t = t0 + r;
        // stage x row (2 floats per thread, coalesced)
        const float2 xv = *(const float2*)(x + (size_t)(b * TT + t) * DD + threadIdx.x * 2);
        *(float2*)&xs[threadIdx.x * 2] = xv;
        __syncthreads();

        unsigned long long acc;
        asm("mov.b64 %0, {%1, %2};" : "=l"(acc) : "f"(0.0f), "f"(0.0f));
#pragma unroll
        for (int i = 0; i < 16; i++) {
            ulonglong2 xp = *(const ulonglong2*)&xs[d0 + 4 * i];   // LDS.128 broadcast
            asm("fma.rn.f32x2 %0, %1, %2, %0;" : "+l"(acc) : "l"(xp.x), "l"(wp[2 * i]));
            asm("fma.rn.f32x2 %0, %1, %2, %0;" : "+l"(acc) : "l"(xp.y), "l"(wp[2 * i + 1]));
        }
        float alo, ahi;
        asm("mov.b64 {%0, %1}, %2;" : "=f"(alo), "=f"(ahi) : "l"(acc));
        part[w][lane] = alo + ahi;
        __syncthreads();

        if (w == 0) {
            float s = bj;
#pragma unroll
            for (int p = 0; p < 8; p++) s += part[p][lane];
            g_logits[(size_t)(b * TT + t) * UU + lane] = s;
        }
    }
}

// ---------------------------------------------------------------------------
// 31-node max+argmax tree. '>' (right wins only if strictly greater) over a
// left-lower-index tree == first-occurrence argmax (jnp.argmax semantics).
// ---------------------------------------------------------------------------
__device__ __forceinline__ void argmax32(const float* __restrict__ c, float& mval, int& midx)
{
    float v[16]; int id[16];
#pragma unroll
    for (int i = 0; i < 16; i++) {
        bool p = c[2 * i + 1] > c[2 * i];
        v[i]  = p ? c[2 * i + 1] : c[2 * i];
        id[i] = p ? (2 * i + 1) : (2 * i);
    }
#pragma unroll
    for (int n = 8; n >= 1; n >>= 1) {
#pragma unroll
        for (int i = 0; i < n; i++) {
            bool p = v[2 * i + 1] > v[2 * i];
            v[i]  = p ? v[2 * i + 1] : v[2 * i];
            id[i] = p ? id[2 * i + 1] : id[2 * i];
        }
    }
    mval = v[0]; midx = id[0];
}

// One Viterbi forward step (lane = next tag j).
__device__ __forceinline__ void vstep(
    float* __restrict__ ab, unsigned& aoff, const float tc[32], float lgv,
    int t, unsigned& pk, unsigned* __restrict__ bps, int lane, int len)
{
    __syncwarp();
    const float4* ap = (const float4*)(ab + aoff);
    float c[32];
#pragma unroll
    for (int q = 0; q < 8; q++) {
        float4 f = ap[q];
        c[4 * q + 0] = f.x + tc[4 * q + 0];
        c[4 * q + 1] = f.y + tc[4 * q + 1];
        c[4 * q + 2] = f.z + tc[4 * q + 2];
        c[4 * q + 3] = f.w + tc[4 * q + 3];
    }
    float m; int bi;
    argmax32(c, m, bi);
    aoff ^= 32;
    ab[aoff + lane] = m + lgv;
    pk |= (unsigned)bi << (8 * (t & 3));
    if (((t & 3) == 3) || (t == len - 1)) {      // uniform
        bps[(t >> 2) * 32 + lane] = pk;
        pk = 0;
    }
}

// ---------------------------------------------------------------------------
// Kernel 2: Viterbi forward + backtrace. grid = 64 blocks, 1 warp each.
// ---------------------------------------------------------------------------
__global__ void __launch_bounds__(32) viterbi_kernel(
    const float* __restrict__ trans, const int* __restrict__ nw, float* __restrict__ out)
{
    const int b    = blockIdx.x;
    const int lane = threadIdx.x;
    const int len  = nw[b];
    const float* lg = g_logits + (size_t)b * TT * UU;
    unsigned*    bps = g_bps  + (size_t)b * (TT / 4) * UU;

    float tc[32];
#pragma unroll
    for (int k = 0; k < 32; k++) tc[k] = trans[k * UU + lane];   // trans column 'lane'

    __shared__ __align__(16) float ab[64];
    unsigned aoff = 0;
    ab[lane] = lg[lane];                          // alpha0 = logits[:,0]
    unsigned pk = 0;

    // ---- forward, groups of 4 with double-buffered logit prefetch ----
    float lA[4], lB[4];
#pragma unroll
    for (int u = 0; u < 4; u++) lA[u] = lg[(1 + u) * UU + lane];   // padded buffer: safe

    for (int s = 1; s < len; s += 4) {
#pragma unroll
        for (int u = 0; u < 4; u++) lB[u] = lg[(s + 4 + u) * UU + lane];
#pragma unroll
        for (int u = 0; u < 4; u++) {
            const int t = s + u;
            if (t < len) vstep(ab, aoff, tc, lA[u], t, pk, bps, lane, len);
        }
#pragma unroll
        for (int u = 0; u < 4; u++) lA[u] = lB[u];
    }
    __syncwarp();

    // ---- final argmax: best_score + last_tag ----
    float fa[32];
#pragma unroll
    for (int q = 0; q < 8; q++) {
        float4 f = ((const float4*)(ab + aoff))[q];
        fa[4 * q + 0] = f.x; fa[4 * q + 1] = f.y;
        fa[4 * q + 2] = f.z; fa[4 * q + 3] = f.w;
    }
    float best; int last;
    argmax32(fa, best, last);
    if (lane == 0) out[BB * TT + b] = best;

    float* pred = out + (size_t)b * TT;
    const float ltf = (float)last;
    // tail fill: pred[t] = last_tag for t in [len-1, T)
    for (int t = len - 1 + lane; t < TT; t += 32) pred[t] = ltf;

    // ---- backtrace (sequential; chain = one shfl + byte extract per step) ----
    int tag = last;
    int t = len - 1;
    if (t >= 1) {
        int q = t >> 2;
        unsigned w0 = bps[q * 32 + lane];
        unsigned w1 = (q >= 1) ? bps[(q - 1) * 32 + lane] : 0u;
        unsigned w2 = (q >= 2) ? bps[(q - 2) * 32 + lane] : 0u;

        // step at t = len-1 (pred[len-1] already written by fill)
        unsigned wv = __shfl_sync(0xffffffffu, w0, tag);
        tag = (int)((wv >> (8 * (t & 3))) & 31u);
        if ((t & 3) == 0) { w0 = w1; w1 = w2; int qn = (t >> 2) - 3; w2 = (qn >= 0) ? bps[qn * 32 + lane] : 0u; }
        t--;

        int myval = 0;
        for (; t >= 1; t--) {
            if ((t & 31) == lane) myval = tag;                    // record pred[t] = tag
            wv = __shfl_sync(0xffffffffu, w0, tag);
            const int nt = (int)((wv >> (8 * (t & 3))) & 31u);
            if ((t & 31) == 0) {
                const int pos = t + lane;
                if (pos <= len - 2) pred[pos] = (float)myval;     // pos > len-2 handled by fill
            }
            if ((t & 3) == 0) { w0 = w1; w1 = w2; int qn = (t >> 2) - 3; w2 = (qn >= 0) ? bps[qn * 32 + lane] : 0u; }
            tag = nt;
        }
        if (lane >= 1 && lane <= len - 2) pred[lane] = (float)myval;
        if (lane == 0) pred[0] = (float)tag;
    }
    // len == 1: fill already wrote everything (pred[:] = last_tag)
}

// ---------------------------------------------------------------------------
// inputs (metadata order): x f32[64,2048,512], nwords i32[64],
// kernel f32[512,32], chain_kernel f32[32,32], bias f32[32]
// out (float32): pred_ids flattened [64*2048] then best_score [64]
// ---------------------------------------------------------------------------
extern "C" void kernel_launch(void* const* d_in, const int* in_sizes, int n_in,
                              void* d_out, int out_size)
{
    const float* x     = (const float*)d_in[0];
    const int*   nw    = (const int*)  d_in[1];
    const float* W     = (const float*)d_in[2];
    const float* trans = (const float*)d_in[3];
    const float* bias  = (const float*)d_in[4];
    float* out = (float*)d_out;

    gemm_kernel<<<BB * 16, 256>>>(x, W, bias, nw);
    viterbi_kernel<<<BB, 32>>>(trans, nw, out);
}

// round 10
// speedup vs baseline: 1.2072x; 1.2072x over previous
#include <cuda_runtime.h>
#include <cstdint>

#define BB 64
#define TT 2048
#define DD 512
#define UU 32

// Scratch (device globals: allowed, no runtime allocation)
__device__ float    g_logits[(BB * TT + 16) * UU];   // padded for prefetch overrun
__device__ unsigned g_bps[BB * (TT / 4) * UU];       // backpointers, 4 steps packed per u32

// ---------------------------------------------------------------------------
// Kernel 1: logits = x @ W + bias, fp32 via packed f32x2 FMA.
// grid = 64 batches * 16 chunks of 128 rows, block = 256 threads (8 warps).
// Warp w owns d in [64w, 64w+64) with W column pairs in registers.
// 4-row groups with register prefetch (MLP=4) and 3 syncs per group.
// Rows with t >= nwords[b] are skipped entirely.
// ---------------------------------------------------------------------------
__global__ void __launch_bounds__(256, 2) gemm_kernel(
    const float* __restrict__ x, const float* __restrict__ W,
    const float* __restrict__ bias, const int* __restrict__ nw)
{
    const int b    = blockIdx.x >> 4;
    const int t0   = (blockIdx.x & 15) * 128;
    const int len  = nw[b];
    if (t0 >= len) return;                       // uniform per block

    const int tid  = threadIdx.x;
    const int w    = tid >> 5;
    const int lane = tid & 31;
    const int d0   = w * 64;

    // W pairs in registers: wp[i] = (W[d0+2i][lane], W[d0+2i+1][lane])
    unsigned long long wp[32];
#pragma unroll
    for (int i = 0; i < 32; i++) {
        float lo = W[(d0 + 2 * i) * UU + lane];
        float hi = W[(d0 + 2 * i + 1) * UU + lane];
        asm("mov.b64 %0, {%1, %2};" : "=l"(wp[i]) : "f"(lo), "f"(hi));
    }

    __shared__ __align__(16) float xs[4][DD];    // 8 KB staging for 4 rows
    __shared__ float part[4][8][32];             // 4 KB partials
    const float bj = bias[lane];
    const int rmax = min(128, len - t0);
    const size_t rowbase = (size_t)(b * TT + t0);

    // prefetch group 0
    float2 xv[4];
#pragma unroll
    for (int u = 0; u < 4; u++)
        if (u < rmax) xv[u] = *(const float2*)(x + (rowbase + u) * DD + tid * 2);

    for (int g = 0; g < rmax; g += 4) {
        // stage current group
#pragma unroll
        for (int u = 0; u < 4; u++)
            if (g + u < rmax) *(float2*)&xs[u][tid * 2] = xv[u];
        __syncthreads();                          // S1: xs ready (and prev compute done)

        // prefetch next group (in flight during compute)
#pragma unroll
        for (int u = 0; u < 4; u++)
            if (g + 4 + u < rmax) xv[u] = *(const float2*)(x + (rowbase + g + 4 + u) * DD + tid * 2);

        float rs[4];
#pragma unroll
        for (int u = 0; u < 4; u++) {
            if (g + u < rmax) {
                unsigned long long acc;
                asm("mov.b64 %0, {%1, %2};" : "=l"(acc) : "f"(0.0f), "f"(0.0f));
#pragma unroll
                for (int i = 0; i < 16; i++) {
                    ulonglong2 xp = *(const ulonglong2*)&xs[u][d0 + 4 * i];   // LDS.128
                    asm("fma.rn.f32x2 %0, %1, %2, %0;" : "+l"(acc) : "l"(xp.x), "l"(wp[2 * i]));
                    asm("fma.rn.f32x2 %0, %1, %2, %0;" : "+l"(acc) : "l"(xp.y), "l"(wp[2 * i + 1]));
                }
                float alo, ahi;
                asm("mov.b64 {%0, %1}, %2;" : "=f"(alo), "=f"(ahi) : "l"(acc));
                rs[u] = alo + ahi;
            }
        }
#pragma unroll
        for (int u = 0; u < 4; u++)
            if (g + u < rmax) part[u][w][lane] = rs[u];
        __syncthreads();                          // S2: partials ready

        if (w < 4 && g + w < rmax) {              // warps 0-3 reduce one row each
            float s = bj;
#pragma unroll
            for (int p = 0; p < 8; p++) s += part[w][p][lane];
            g_logits[(rowbase + g + w) * UU + lane] = s;
        }
        __syncthreads();                          // S3: part/xs reusable
    }
}

// ---------------------------------------------------------------------------
// 31-node max+argmax tree over a lane-local array (first-occurrence argmax).
// ---------------------------------------------------------------------------
__device__ __forceinline__ void argmax32(const float* __restrict__ c, float& mval, int& midx)
{
    float v[16]; int id[16];
#pragma unroll
    for (int i = 0; i < 16; i++) {
        bool p = c[2 * i + 1] > c[2 * i];
        v[i]  = p ? c[2 * i + 1] : c[2 * i];
        id[i] = p ? (2 * i + 1) : (2 * i);
    }
#pragma unroll
    for (int n = 8; n >= 1; n >>= 1) {
#pragma unroll
        for (int i = 0; i < n; i++) {
            bool p = v[2 * i + 1] > v[2 * i];
            v[i]  = p ? v[2 * i + 1] : v[2 * i];
            id[i] = p ? id[2 * i + 1] : id[2 * i];
        }
    }
    mval = v[0]; midx = id[0];
}

// ---------------------------------------------------------------------------
// Kernel 2: Viterbi forward + backtrace. grid = 64 blocks, 4 warps each.
// Warp w reduces prev-tags k in [8w, 8w+8); partials combined per step via
// one barrier; alpha kept replicated in registers (per-lane, all warps).
// ---------------------------------------------------------------------------
__global__ void __launch_bounds__(128) viterbi_kernel(
    const float* __restrict__ trans, const int* __restrict__ nw, float* __restrict__ out)
{
    const int b    = blockIdx.x;
    const int tid  = threadIdx.x;
    const int w    = tid >> 5;
    const int lane = tid & 31;
    const int kb   = w * 8;
    const int len  = nw[b];
    const float* lg  = g_logits + (size_t)b * TT * UU;
    unsigned*    bps = g_bps   + (size_t)b * (TT / 4) * UU;

    float tcw[8];
#pragma unroll
    for (int i = 0; i < 8; i++) tcw[i] = trans[(kb + i) * UU + lane];  // trans[k][lane]

    __shared__ __align__(16) float2 pb[2][4][32];   // double-buffered partials
    __shared__ __align__(16) float fab[32];

    float av = lg[lane];                             // alpha0 = logits[:,0], lane j
    unsigned pk = 0;

    // logits prefetch, 4 steps ahead (padded buffer makes overrun safe)
    float lA[4], lB[4];
#pragma unroll
    for (int u = 0; u < 4; u++) lA[u] = lg[(1 + u) * UU + lane];

    for (int s = 1; s < len; s += 4) {
#pragma unroll
        for (int u = 0; u < 4; u++) lB[u] = lg[(s + 4 + u) * UU + lane];
#pragma unroll
        for (int u = 0; u < 4; u++) {
            const int t = s + u;
            if (t < len) {                           // uniform across block
                // c_k = alpha_k + trans[k][j], k in warp's range (alpha via shfl)
                float c[8];
#pragma unroll
                for (int i = 0; i < 8; i++)
                    c[i] = __shfl_sync(0xffffffffu, av, kb + i) + tcw[i];
                // 7-node partial tree (left = lower k; right wins only if >)
                float v[4]; int id[4];
#pragma unroll
                for (int i = 0; i < 4; i++) {
                    bool p = c[2 * i + 1] > c[2 * i];
                    v[i]  = p ? c[2 * i + 1] : c[2 * i];
                    id[i] = kb + (p ? 2 * i + 1 : 2 * i);
                }
                bool p0 = v[1] > v[0]; float v0 = p0 ? v[1] : v[0]; int i0 = p0 ? id[1] : id[0];
                bool p1 = v[3] > v[2]; float v1 = p1 ? v[3] : v[2]; int i1 = p1 ? id[3] : id[2];
                bool p2 = v1 > v0;  float pvv = p2 ? v1 : v0;  int pii = p2 ? i1 : i0;

                float2* pp = &pb[t & 1][0][0];
                pp[w * 32 + lane] = make_float2(pvv, __int_as_float(pii));
                __syncthreads();
                // redundant combine in every warp (keeps alpha in registers)
                float2 q0 = pp[lane], q1 = pp[32 + lane], q2 = pp[64 + lane], q3 = pp[96 + lane];
                bool a0 = q1.x > q0.x; float m0 = a0 ? q1.x : q0.x; float j0 = a0 ? q1.y : q0.y;
                bool a1 = q3.x > q2.x; float m1 = a1 ? q3.x : q2.x; float j1 = a1 ? q3.y : q2.y;
                bool a2 = m1 > m0;  float m = a2 ? m1 : m0;  int bi = __float_as_int(a2 ? j1 : j0);
                av = m + lA[u];

                if (w == 0) {                        // warp 0 records backpointers
                    pk |= (unsigned)bi << (8 * (t & 3));
                    if (((t & 3) == 3) || (t == len - 1)) {
                        bps[(t >> 2) * 32 + lane] = pk;
                        pk = 0;
                    }
                }
            }
        }
#pragma unroll
        for (int u = 0; u < 4; u++) lA[u] = lB[u];
    }

    // ---- final argmax (computed identically by all threads) ----
    if (w == 0) fab[lane] = av;
    __syncthreads();
    float fa[32];
#pragma unroll
    for (int q = 0; q < 8; q++) {
        float4 f = ((const float4*)fab)[q];
        fa[4 * q + 0] = f.x; fa[4 * q + 1] = f.y;
        fa[4 * q + 2] = f.z; fa[4 * q + 3] = f.w;
    }
    float best; int last;
    argmax32(fa, best, last);
    if (tid == 0) out[BB * TT + b] = best;

    float* pred = out + (size_t)b * TT;
    const float ltf = (float)last;
    // tail fill with all 128 threads: pred[t] = last_tag for t in [len-1, T)
    for (int t = len - 1 + tid; t < TT; t += 128) pred[t] = ltf;

    if (w != 0) return;                              // warps 1-3 done

    // ---- backtrace (warp 0; chain = one shfl + byte extract per step) ----
    int tag = last;
    int t = len - 1;
    if (t >= 1) {
        int q = t >> 2;
        unsigned w0 = bps[q * 32 + lane];
        unsigned w1 = (q >= 1) ? bps[(q - 1) * 32 + lane] : 0u;
        unsigned w2 = (q >= 2) ? bps[(q - 2) * 32 + lane] : 0u;

        // step at t = len-1 (pred[len-1] already written by fill)
        unsigned wv = __shfl_sync(0xffffffffu, w0, tag);
        tag = (int)((wv >> (8 * (t & 3))) & 31u);
        if ((t & 3) == 0) { w0 = w1; w1 = w2; int qn = (t >> 2) - 3; w2 = (qn >= 0) ? bps[qn * 32 + lane] : 0u; }
        t--;

        int myval = 0;
        for (; t >= 1; t--) {
            if ((t & 31) == lane) myval = tag;                    // record pred[t] = tag
            wv = __shfl_sync(0xffffffffu, w0, tag);
            const int nt = (int)((wv >> (8 * (t & 3))) & 31u);
            if ((t & 31) == 0) {
                const int pos = t + lane;
                if (pos <= len - 2) pred[pos] = (float)myval;     // pos > len-2 handled by fill
            }
            if ((t & 3) == 0) { w0 = w1; w1 = w2; int qn = (t >> 2) - 3; w2 = (qn >= 0) ? bps[qn * 32 + lane] : 0u; }
            tag = nt;
        }
        if (lane >= 1 && lane <= len - 2) pred[lane] = (float)myval;
        if (lane == 0) pred[0] = (float)tag;
    }
    // len == 1: fill already wrote everything
}

// ---------------------------------------------------------------------------
// inputs (metadata order): x f32[64,2048,512], nwords i32[64],
// kernel f32[512,32], chain_kernel f32[32,32], bias f32[32]
// out (float32): pred_ids flattened [64*2048] then best_score [64]
// ---------------------------------------------------------------------------
extern "C" void kernel_launch(void* const* d_in, const int* in_sizes, int n_in,
                              void* d_out, int out_size)
{
    const float* x     = (const float*)d_in[0];
    const int*   nw    = (const int*)  d_in[1];
    const float* W     = (const float*)d_in[2];
    const float* trans = (const float*)d_in[3];
    const float* bias  = (const float*)d_in[4];
    float* out = (float*)d_out;

    gemm_kernel<<<BB * 16, 256>>>(x, W, bias, nw);
    viterbi_kernel<<<BB, 128>>>(trans, nw, out);
}